// round 1
// baseline (speedup 1.0000x reference)
#include <cuda_runtime.h>
#include <cuda_bf16.h>

// SpatialTransformer: 3D trilinear grid-sample, border padding, align_corners=True.
// Fixed shapes: img [2,1,160,192,224], flow [2,3,160,192,224], out [2,1,160,192,224].
//
// Reference math:
//   px = (x + flow0 + 1) * 0.5 * (W-1)   (x channel goes through grid_sample unnorm)
//   py =  y + flow1
//   pz =  z + flow2
//   clamp to [0, dim-1], trilinear interp.

#define DD 160
#define HH 192
#define WW 224
#define NVOX (DD * HH * WW)   // 6,881,280
#define NB 2

__global__ __launch_bounds__(256) void st3d_kernel(
    const float* __restrict__ img,
    const float* __restrict__ flow,
    float* __restrict__ out)
{
    const int tid = blockIdx.x * blockDim.x + threadIdx.x;
    const long long idx4 = (long long)tid * 4;
    if (idx4 >= (long long)NB * NVOX) return;

    const int b = (int)(idx4 / NVOX);
    const int i = (int)(idx4 - (long long)b * NVOX);   // multiple of 4, row-aligned (WW % 4 == 0)

    const int z = i / (HH * WW);
    const int rem = i - z * (HH * WW);
    const int y = rem / WW;
    const int x = rem - y * WW;

    const float* fb = flow + (size_t)b * 3 * NVOX;
    const float4 f0 = *reinterpret_cast<const float4*>(fb + i);             // x-flow
    const float4 f1 = *reinterpret_cast<const float4*>(fb + NVOX + i);      // y-flow
    const float4 f2 = *reinterpret_cast<const float4*>(fb + 2 * NVOX + i);  // z-flow

    const float* im = img + (size_t)b * NVOX;   // C = 1

    const float f0a[4] = {f0.x, f0.y, f0.z, f0.w};
    const float f1a[4] = {f1.x, f1.y, f1.z, f1.w};
    const float f2a[4] = {f2.x, f2.y, f2.z, f2.w};

    float4 o;
    float* op = reinterpret_cast<float*>(&o);

    #pragma unroll
    for (int k = 0; k < 4; ++k) {
        // --- coordinate computation (matches reference exactly) ---
        float px = ((float)(x + k) + f0a[k] + 1.0f) * 0.5f * (float)(WW - 1);
        float py = (float)y + f1a[k];
        float pz = (float)z + f2a[k];

        px = fminf(fmaxf(px, 0.0f), (float)(WW - 1));
        py = fminf(fmaxf(py, 0.0f), (float)(HH - 1));
        pz = fminf(fmaxf(pz, 0.0f), (float)(DD - 1));

        const float x0f = floorf(px);
        const float y0f = floorf(py);
        const float z0f = floorf(pz);
        const float fx = px - x0f;
        const float fy = py - y0f;
        const float fz = pz - z0f;

        const int x0 = (int)x0f;
        const int y0 = (int)y0f;
        const int z0 = (int)z0f;
        const int x1 = min(x0 + 1, WW - 1);
        const int y1 = min(y0 + 1, HH - 1);
        const int z1 = min(z0 + 1, DD - 1);

        // --- 8-corner gather ---
        const long long zb0 = (long long)z0 * (HH * WW);
        const long long zb1 = (long long)z1 * (HH * WW);
        const int yb0 = y0 * WW;
        const int yb1 = y1 * WW;

        const float c000 = __ldg(im + zb0 + yb0 + x0);
        const float c001 = __ldg(im + zb0 + yb0 + x1);
        const float c010 = __ldg(im + zb0 + yb1 + x0);
        const float c011 = __ldg(im + zb0 + yb1 + x1);
        const float c100 = __ldg(im + zb1 + yb0 + x0);
        const float c101 = __ldg(im + zb1 + yb0 + x1);
        const float c110 = __ldg(im + zb1 + yb1 + x0);
        const float c111 = __ldg(im + zb1 + yb1 + x1);

        // --- trilinear lerp (same association order as reference) ---
        const float c00 = c000 + (c001 - c000) * fx;
        const float c01 = c010 + (c011 - c010) * fx;
        const float c10 = c100 + (c101 - c100) * fx;
        const float c11 = c110 + (c111 - c110) * fx;
        const float c0  = c00 + (c01 - c00) * fy;
        const float c1  = c10 + (c11 - c10) * fy;
        op[k] = c0 + (c1 - c0) * fz;
    }

    *reinterpret_cast<float4*>(out + (size_t)b * NVOX + i) = o;
}

extern "C" void kernel_launch(void* const* d_in, const int* in_sizes, int n_in,
                              void* d_out, int out_size)
{
    const float* img  = (const float*)d_in[0];
    const float* flow = (const float*)d_in[1];
    float* out = (float*)d_out;

    const long long total4 = (long long)NB * NVOX / 4;   // 3,440,640 threads
    const int threads = 256;
    const int blocks = (int)((total4 + threads - 1) / threads);

    st3d_kernel<<<blocks, threads>>>(img, flow, out);
}

// round 2
// speedup vs baseline: 2.6298x; 2.6298x over previous
#include <cuda_runtime.h>
#include <cuda_bf16.h>

// SpatialTransformer: 3D trilinear grid-sample, border padding, align_corners=True.
// img [2,1,160,192,224], flow [2,3,160,192,224], out [2,1,160,192,224].
//
// px = (x + flow0 + 1) * 0.5 * (W-1)  -> clamps to W-1=223 for nearly all x,
// so ~98% of samples reduce to a bilinear interp on the x=223 border slice.
// Kernel 1 compacts that slice (245 KB, L1-resident); kernel 2 uses it.

#define DD 160
#define HH 192
#define WW 224
#define HW (HH * WW)
#define NVOX (DD * HH * WW)   // 6,881,280
#define NB 2
#define NSLICE (NB * DD * HH) // 61,440

__device__ float g_bslice[NSLICE];   // [b][z][y] = img[b][z][y][223]

__global__ __launch_bounds__(256) void extract_border_kernel(
    const float* __restrict__ img)
{
    int idx = blockIdx.x * blockDim.x + threadIdx.x;
    if (idx >= NSLICE) return;
    int b = idx / (DD * HH);
    int r = idx - b * (DD * HH);      // z*HH + y
    int z = r / HH;
    int y = r - z * HH;
    g_bslice[idx] = img[(size_t)b * NVOX + (size_t)z * HW + y * WW + (WW - 1)];
}

__global__ __launch_bounds__(256) void st3d_kernel(
    const float* __restrict__ img,
    const float* __restrict__ flow,
    float* __restrict__ out)
{
    const int tid = blockIdx.x * blockDim.x + threadIdx.x;
    const long long idx4 = (long long)tid * 4;
    if (idx4 >= (long long)NB * NVOX) return;

    const int b = (int)(idx4 / NVOX);
    const int i = (int)(idx4 - (long long)b * NVOX);   // multiple of 4, row-aligned

    const int z = i / HW;
    const int rem = i - z * HW;
    const int y = rem / WW;
    const int x = rem - y * WW;

    const float* fb = flow + (size_t)b * 3 * NVOX;
    const float4 f0 = *reinterpret_cast<const float4*>(fb + i);
    const float4 f1 = *reinterpret_cast<const float4*>(fb + NVOX + i);
    const float4 f2 = *reinterpret_cast<const float4*>(fb + 2 * NVOX + i);

    const float* im = img + (size_t)b * NVOX;
    const float* bs = g_bslice + b * (DD * HH);

    const float f0a[4] = {f0.x, f0.y, f0.z, f0.w};
    const float f1a[4] = {f1.x, f1.y, f1.z, f1.w};
    const float f2a[4] = {f2.x, f2.y, f2.z, f2.w};

    float4 o;
    float* op = reinterpret_cast<float*>(&o);

    #pragma unroll
    for (int k = 0; k < 4; ++k) {
        float px = ((float)(x + k) + f0a[k] + 1.0f) * 0.5f * (float)(WW - 1);
        float py = (float)y + f1a[k];
        float pz = (float)z + f2a[k];

        px = fminf(fmaxf(px, 0.0f), (float)(WW - 1));
        py = fminf(fmaxf(py, 0.0f), (float)(HH - 1));
        pz = fminf(fmaxf(pz, 0.0f), (float)(DD - 1));

        const float x0f = floorf(px);
        const float y0f = floorf(py);
        const float z0f = floorf(pz);
        const float fy = py - y0f;
        const float fz = pz - z0f;

        const int x0 = (int)x0f;
        const int y0 = (int)y0f;
        const int z0 = (int)z0f;
        const int y1 = min(y0 + 1, HH - 1);
        const int z1 = min(z0 + 1, DD - 1);

        float res;
        if (x0 == WW - 1) {
            // border fast path: fx == 0, only column 223 contributes.
            // bilinear over compact L1-resident slice [z][y].
            const float v00 = bs[z0 * HH + y0];
            const float v01 = bs[z0 * HH + y1];
            const float v10 = bs[z1 * HH + y0];
            const float v11 = bs[z1 * HH + y1];
            const float c0 = v00 + (v01 - v00) * fy;
            const float c1 = v10 + (v11 - v10) * fy;
            res = c0 + (c1 - c0) * fz;
        } else {
            const float fx = px - x0f;
            const int x1 = min(x0 + 1, WW - 1);
            const long long zb0 = (long long)z0 * HW;
            const long long zb1 = (long long)z1 * HW;
            const int yb0 = y0 * WW;
            const int yb1 = y1 * WW;

            const float c000 = __ldg(im + zb0 + yb0 + x0);
            const float c001 = __ldg(im + zb0 + yb0 + x1);
            const float c010 = __ldg(im + zb0 + yb1 + x0);
            const float c011 = __ldg(im + zb0 + yb1 + x1);
            const float c100 = __ldg(im + zb1 + yb0 + x0);
            const float c101 = __ldg(im + zb1 + yb0 + x1);
            const float c110 = __ldg(im + zb1 + yb1 + x0);
            const float c111 = __ldg(im + zb1 + yb1 + x1);

            const float c00 = c000 + (c001 - c000) * fx;
            const float c01 = c010 + (c011 - c010) * fx;
            const float c10 = c100 + (c101 - c100) * fx;
            const float c11 = c110 + (c111 - c110) * fx;
            const float c0 = c00 + (c01 - c00) * fy;
            const float c1 = c10 + (c11 - c10) * fy;
            res = c0 + (c1 - c0) * fz;
        }
        op[k] = res;
    }

    *reinterpret_cast<float4*>(out + (size_t)b * NVOX + i) = o;
}

extern "C" void kernel_launch(void* const* d_in, const int* in_sizes, int n_in,
                              void* d_out, int out_size)
{
    const float* img  = (const float*)d_in[0];
    const float* flow = (const float*)d_in[1];
    float* out = (float*)d_out;

    extract_border_kernel<<<(NSLICE + 255) / 256, 256>>>(img);

    const long long total4 = (long long)NB * NVOX / 4;
    const int threads = 256;
    const int blocks = (int)((total4 + threads - 1) / threads);
    st3d_kernel<<<blocks, threads>>>(img, flow, out);
}

// round 3
// speedup vs baseline: 3.0065x; 1.1432x over previous
#include <cuda_runtime.h>
#include <cuda_bf16.h>

// SpatialTransformer: 3D trilinear grid-sample, border padding, align_corners=True.
// img [2,1,160,192,224], flow [2,3,160,192,224], out [2,1,160,192,224].
//
// px = (x + flow0 + 1)*0.5*(W-1) clamps to W-1=223 for ~98% of voxels (fx=0),
// reducing those to bilinear interp on the x=223 border slice (compacted into
// g_bslice, 245 KB, L2/L1-resident). 8 outputs/thread -> 6 front-batched
// LDG.128 for deep MLP; streaming cache hints keep the slice resident.

#define DD 160
#define HH 192
#define WW 224
#define HW (HH * WW)
#define NVOX (DD * HH * WW)   // 6,881,280
#define NB 2
#define NSLICE (NB * DD * HH) // 61,440

__device__ float g_bslice[NSLICE];   // [b][z][y] = img[b][z][y][223]

__global__ __launch_bounds__(256) void extract_border_kernel(
    const float* __restrict__ img)
{
    int idx = blockIdx.x * blockDim.x + threadIdx.x;
    if (idx >= NSLICE) return;
    int b = idx / (DD * HH);
    int r = idx - b * (DD * HH);      // z*HH + y
    int z = r / HH;
    int y = r - z * HH;
    g_bslice[idx] = img[(size_t)b * NVOX + (size_t)z * HW + y * WW + (WW - 1)];
}

__global__ __launch_bounds__(256) void st3d_kernel(
    const float* __restrict__ img,
    const float* __restrict__ flow,
    float* __restrict__ out)
{
    const int tid = blockIdx.x * blockDim.x + threadIdx.x;
    const long long idx8 = (long long)tid * 8;
    if (idx8 >= (long long)NB * NVOX) return;

    const int b = (int)(idx8 / NVOX);
    const int i = (int)(idx8 - (long long)b * NVOX);   // multiple of 8, row-aligned

    const int z = i / HW;
    const int rem = i - z * HW;
    const int y = rem / WW;
    const int x = rem - y * WW;

    const float* fb = flow + (size_t)b * 3 * NVOX;

    // 6 front-batched 128-bit streaming loads (evict-first: flow is read once)
    const float4 f0lo = __ldcs(reinterpret_cast<const float4*>(fb + i));
    const float4 f0hi = __ldcs(reinterpret_cast<const float4*>(fb + i + 4));
    const float4 f1lo = __ldcs(reinterpret_cast<const float4*>(fb + NVOX + i));
    const float4 f1hi = __ldcs(reinterpret_cast<const float4*>(fb + NVOX + i + 4));
    const float4 f2lo = __ldcs(reinterpret_cast<const float4*>(fb + 2 * NVOX + i));
    const float4 f2hi = __ldcs(reinterpret_cast<const float4*>(fb + 2 * NVOX + i + 4));

    const float* im = img + (size_t)b * NVOX;
    const float* bs = g_bslice + b * (DD * HH);

    const float f0a[8] = {f0lo.x, f0lo.y, f0lo.z, f0lo.w, f0hi.x, f0hi.y, f0hi.z, f0hi.w};
    const float f1a[8] = {f1lo.x, f1lo.y, f1lo.z, f1lo.w, f1hi.x, f1hi.y, f1hi.z, f1hi.w};
    const float f2a[8] = {f2lo.x, f2lo.y, f2lo.z, f2lo.w, f2hi.x, f2hi.y, f2hi.z, f2hi.w};

    float oa[8];

    #pragma unroll
    for (int k = 0; k < 8; ++k) {
        float px = ((float)(x + k) + f0a[k] + 1.0f) * 0.5f * (float)(WW - 1);
        float py = (float)y + f1a[k];
        float pz = (float)z + f2a[k];

        px = fminf(fmaxf(px, 0.0f), (float)(WW - 1));
        py = fminf(fmaxf(py, 0.0f), (float)(HH - 1));
        pz = fminf(fmaxf(pz, 0.0f), (float)(DD - 1));

        const float x0f = floorf(px);
        const float y0f = floorf(py);
        const float z0f = floorf(pz);
        const float fy = py - y0f;
        const float fz = pz - z0f;

        const int x0 = (int)x0f;
        const int y0 = (int)y0f;
        const int z0 = (int)z0f;
        const int y1 = min(y0 + 1, HH - 1);
        const int z1 = min(z0 + 1, DD - 1);

        float res;
        if (x0 == WW - 1) {
            // border fast path: fx == 0, only column 223 contributes.
            const float v00 = __ldg(bs + z0 * HH + y0);
            const float v01 = __ldg(bs + z0 * HH + y1);
            const float v10 = __ldg(bs + z1 * HH + y0);
            const float v11 = __ldg(bs + z1 * HH + y1);
            const float c0 = v00 + (v01 - v00) * fy;
            const float c1 = v10 + (v11 - v10) * fy;
            res = c0 + (c1 - c0) * fz;
        } else {
            const float fx = px - x0f;
            const int x1 = min(x0 + 1, WW - 1);
            const long long zb0 = (long long)z0 * HW;
            const long long zb1 = (long long)z1 * HW;
            const int yb0 = y0 * WW;
            const int yb1 = y1 * WW;

            const float c000 = __ldg(im + zb0 + yb0 + x0);
            const float c001 = __ldg(im + zb0 + yb0 + x1);
            const float c010 = __ldg(im + zb0 + yb1 + x0);
            const float c011 = __ldg(im + zb0 + yb1 + x1);
            const float c100 = __ldg(im + zb1 + yb0 + x0);
            const float c101 = __ldg(im + zb1 + yb0 + x1);
            const float c110 = __ldg(im + zb1 + yb1 + x0);
            const float c111 = __ldg(im + zb1 + yb1 + x1);

            const float c00 = c000 + (c001 - c000) * fx;
            const float c01 = c010 + (c011 - c010) * fx;
            const float c10 = c100 + (c101 - c100) * fx;
            const float c11 = c110 + (c111 - c110) * fx;
            const float c0 = c00 + (c01 - c00) * fy;
            const float c1 = c10 + (c11 - c10) * fy;
            res = c0 + (c1 - c0) * fz;
        }
        oa[k] = res;
    }

    float* ob = out + (size_t)b * NVOX + i;
    __stcs(reinterpret_cast<float4*>(ob),     make_float4(oa[0], oa[1], oa[2], oa[3]));
    __stcs(reinterpret_cast<float4*>(ob + 4), make_float4(oa[4], oa[5], oa[6], oa[7]));
}

extern "C" void kernel_launch(void* const* d_in, const int* in_sizes, int n_in,
                              void* d_out, int out_size)
{
    const float* img  = (const float*)d_in[0];
    const float* flow = (const float*)d_in[1];
    float* out = (float*)d_out;

    extract_border_kernel<<<(NSLICE + 255) / 256, 256>>>(img);

    const long long total8 = (long long)NB * NVOX / 8;   // 1,720,320 threads
    const int threads = 256;
    const int blocks = (int)((total8 + threads - 1) / threads);
    st3d_kernel<<<blocks, threads>>>(img, flow, out);
}

// round 4
// speedup vs baseline: 3.3193x; 1.1040x over previous
#include <cuda_runtime.h>
#include <cuda_bf16.h>

// SpatialTransformer: 3D trilinear grid-sample, border padding, align_corners=True.
// img [2,1,160,192,224], flow [2,3,160,192,224], out [2,1,160,192,224].
//
// px = (x + flow0 + 1)*0.5*223 clamps to 223 for ~98% of voxels (fx = 0), so those
// outputs are a bilinear interp on the x=223 border slice. We precompute a
// CORNER-PACKED slice bs4[b][z][y] = (s[z][y], s[z][y1], s[z1][y], s[z1][y1])
// (clamps baked in), so the fast path is ONE aligned LDG.128 + 6 flops.
// 983 KB -> L2-resident; flow/out use streaming hints to protect it.

#define DD 160
#define HH 192
#define WW 224
#define HW (HH * WW)
#define NVOX (DD * HH * WW)   // 6,881,280
#define NB 2
#define NSLICE (NB * DD * HH) // 61,440

__device__ float4 g_bs4[NSLICE];   // corner-packed border slice

__global__ __launch_bounds__(256) void build_bs4_kernel(
    const float* __restrict__ img)
{
    int idx = blockIdx.x * blockDim.x + threadIdx.x;
    if (idx >= NSLICE) return;
    int b = idx / (DD * HH);
    int r = idx - b * (DD * HH);      // z*HH + y
    int z = r / HH;
    int y = r - z * HH;
    int y1 = min(y + 1, HH - 1);
    int z1 = min(z + 1, DD - 1);

    const float* im = img + (size_t)b * NVOX + (WW - 1);
    float4 v;
    v.x = __ldg(im + (size_t)z  * HW + y  * WW);
    v.y = __ldg(im + (size_t)z  * HW + y1 * WW);
    v.z = __ldg(im + (size_t)z1 * HW + y  * WW);
    v.w = __ldg(im + (size_t)z1 * HW + y1 * WW);
    g_bs4[idx] = v;
}

__global__ __launch_bounds__(256) void st3d_kernel(
    const float* __restrict__ img,
    const float* __restrict__ flow,
    float* __restrict__ out)
{
    const int tid = blockIdx.x * blockDim.x + threadIdx.x;
    const long long idx8 = (long long)tid * 8;
    if (idx8 >= (long long)NB * NVOX) return;

    const int b = (int)(idx8 / NVOX);
    const int i = (int)(idx8 - (long long)b * NVOX);   // multiple of 8, row-aligned

    const int z = i / HW;
    const int rem = i - z * HW;
    const int y = rem / WW;
    const int x = rem - y * WW;

    const float* fb = flow + (size_t)b * 3 * NVOX;

    // 6 front-batched 128-bit streaming loads (flow is read exactly once)
    const float4 f0lo = __ldcs(reinterpret_cast<const float4*>(fb + i));
    const float4 f0hi = __ldcs(reinterpret_cast<const float4*>(fb + i + 4));
    const float4 f1lo = __ldcs(reinterpret_cast<const float4*>(fb + NVOX + i));
    const float4 f1hi = __ldcs(reinterpret_cast<const float4*>(fb + NVOX + i + 4));
    const float4 f2lo = __ldcs(reinterpret_cast<const float4*>(fb + 2 * NVOX + i));
    const float4 f2hi = __ldcs(reinterpret_cast<const float4*>(fb + 2 * NVOX + i + 4));

    const float* im = img + (size_t)b * NVOX;
    const float4* bs4 = g_bs4 + b * (DD * HH);

    const float f0a[8] = {f0lo.x, f0lo.y, f0lo.z, f0lo.w, f0hi.x, f0hi.y, f0hi.z, f0hi.w};
    const float f1a[8] = {f1lo.x, f1lo.y, f1lo.z, f1lo.w, f1hi.x, f1hi.y, f1hi.z, f1hi.w};
    const float f2a[8] = {f2lo.x, f2lo.y, f2lo.z, f2lo.w, f2hi.x, f2hi.y, f2hi.z, f2hi.w};

    float oa[8];

    #pragma unroll
    for (int k = 0; k < 8; ++k) {
        // raw px (before clamp); (a)*0.5f*223.0f == a*111.5f bitwise (0.5*223 exact)
        const float pxr = ((float)(x + k) + f0a[k] + 1.0f) * 111.5f;

        float py = (float)y + f1a[k];
        float pz = (float)z + f2a[k];
        py = fminf(fmaxf(py, 0.0f), (float)(HH - 1));
        pz = fminf(fmaxf(pz, 0.0f), (float)(DD - 1));

        const float y0f = floorf(py);
        const float z0f = floorf(pz);
        const float fy = py - y0f;
        const float fz = pz - z0f;
        const int y0 = (int)y0f;
        const int z0 = (int)z0f;

        float res;
        if (pxr >= (float)(WW - 1)) {
            // border fast path: fx == 0; all 4 corners in one packed LDG.128
            const float4 v = __ldg(bs4 + z0 * HH + y0);
            const float c0 = v.x + (v.y - v.x) * fy;
            const float c1 = v.z + (v.w - v.z) * fy;
            res = c0 + (c1 - c0) * fz;
        } else {
            const float px = fmaxf(pxr, 0.0f);      // px < 223 here
            const float x0f = floorf(px);
            const float fx = px - x0f;
            const int x0 = (int)x0f;
            const int x1 = min(x0 + 1, WW - 1);
            const int y1 = min(y0 + 1, HH - 1);
            const int z1 = min(z0 + 1, DD - 1);

            const long long zb0 = (long long)z0 * HW;
            const long long zb1 = (long long)z1 * HW;
            const int yb0 = y0 * WW;
            const int yb1 = y1 * WW;

            const float c000 = __ldg(im + zb0 + yb0 + x0);
            const float c001 = __ldg(im + zb0 + yb0 + x1);
            const float c010 = __ldg(im + zb0 + yb1 + x0);
            const float c011 = __ldg(im + zb0 + yb1 + x1);
            const float c100 = __ldg(im + zb1 + yb0 + x0);
            const float c101 = __ldg(im + zb1 + yb0 + x1);
            const float c110 = __ldg(im + zb1 + yb1 + x0);
            const float c111 = __ldg(im + zb1 + yb1 + x1);

            const float c00 = c000 + (c001 - c000) * fx;
            const float c01 = c010 + (c011 - c010) * fx;
            const float c10 = c100 + (c101 - c100) * fx;
            const float c11 = c110 + (c111 - c110) * fx;
            const float c0 = c00 + (c01 - c00) * fy;
            const float c1 = c10 + (c11 - c10) * fy;
            res = c0 + (c1 - c0) * fz;
        }
        oa[k] = res;
    }

    float* ob = out + (size_t)b * NVOX + i;
    __stcs(reinterpret_cast<float4*>(ob),     make_float4(oa[0], oa[1], oa[2], oa[3]));
    __stcs(reinterpret_cast<float4*>(ob + 4), make_float4(oa[4], oa[5], oa[6], oa[7]));
}

extern "C" void kernel_launch(void* const* d_in, const int* in_sizes, int n_in,
                              void* d_out, int out_size)
{
    const float* img  = (const float*)d_in[0];
    const float* flow = (const float*)d_in[1];
    float* out = (float*)d_out;

    build_bs4_kernel<<<(NSLICE + 255) / 256, 256>>>(img);

    const long long total8 = (long long)NB * NVOX / 8;   // 1,720,320 threads
    const int threads = 256;
    const int blocks = (int)((total8 + threads - 1) / threads);
    st3d_kernel<<<blocks, threads>>>(img, flow, out);
}

// round 5
// speedup vs baseline: 3.3252x; 1.0018x over previous
#include <cuda_runtime.h>
#include <cuda_bf16.h>

// SpatialTransformer: 3D trilinear grid-sample, border padding, align_corners=True.
// img [2,1,160,192,224], flow [2,3,160,192,224], out [2,1,160,192,224].
//
// px = (x + flow0 + 1)*0.5*223 clamps to 223 for ~98% of voxels (fx = 0), so those
// outputs are a bilinear interp on the x=223 border slice. Precomputed
// CORNER-PACKED slice bs4[b][z][y] = (s[z][y], s[z][y1], s[z1][y], s[z1][y1])
// (clamps baked in) -> fast path is ONE aligned LDG.128 + 6 flops.
// R5: 4 outputs/thread to cut regs (64 -> ~46) and raise occupancy (32 -> 40+
// warps/SM); warp-level parallelism covers the L2/DRAM latency.

#define DD 160
#define HH 192
#define WW 224
#define HW (HH * WW)
#define NVOX (DD * HH * WW)   // 6,881,280
#define NB 2
#define NSLICE (NB * DD * HH) // 61,440

__device__ float4 g_bs4[NSLICE];   // corner-packed border slice

__global__ __launch_bounds__(256) void build_bs4_kernel(
    const float* __restrict__ img)
{
    int idx = blockIdx.x * blockDim.x + threadIdx.x;
    if (idx >= NSLICE) return;
    int b = idx / (DD * HH);
    int r = idx - b * (DD * HH);      // z*HH + y
    int z = r / HH;
    int y = r - z * HH;
    int y1 = min(y + 1, HH - 1);
    int z1 = min(z + 1, DD - 1);

    const float* im = img + (size_t)b * NVOX + (WW - 1);
    float4 v;
    v.x = __ldg(im + (size_t)z  * HW + y  * WW);
    v.y = __ldg(im + (size_t)z  * HW + y1 * WW);
    v.z = __ldg(im + (size_t)z1 * HW + y  * WW);
    v.w = __ldg(im + (size_t)z1 * HW + y1 * WW);
    g_bs4[idx] = v;
}

__global__ __launch_bounds__(256) void st3d_kernel(
    const float* __restrict__ img,
    const float* __restrict__ flow,
    float* __restrict__ out)
{
    const int tid = blockIdx.x * blockDim.x + threadIdx.x;
    const long long idx4 = (long long)tid * 4;
    if (idx4 >= (long long)NB * NVOX) return;

    const int b = (int)(idx4 / NVOX);
    const int i = (int)(idx4 - (long long)b * NVOX);   // multiple of 4, row-aligned

    const int z = i / HW;
    const int rem = i - z * HW;
    const int y = rem / WW;
    const int x = rem - y * WW;

    const float* fb = flow + (size_t)b * 3 * NVOX;

    // 3 front-batched 128-bit streaming loads (flow is read exactly once)
    const float4 f0 = __ldcs(reinterpret_cast<const float4*>(fb + i));
    const float4 f1 = __ldcs(reinterpret_cast<const float4*>(fb + NVOX + i));
    const float4 f2 = __ldcs(reinterpret_cast<const float4*>(fb + 2 * NVOX + i));

    const float* im = img + (size_t)b * NVOX;
    const float4* bs4 = g_bs4 + b * (DD * HH);

    const float f0a[4] = {f0.x, f0.y, f0.z, f0.w};
    const float f1a[4] = {f1.x, f1.y, f1.z, f1.w};
    const float f2a[4] = {f2.x, f2.y, f2.z, f2.w};

    float oa[4];

    #pragma unroll
    for (int k = 0; k < 4; ++k) {
        // raw px (before clamp); *0.5f*223.0f == *111.5f bitwise (0.5*223 exact)
        const float pxr = ((float)(x + k) + f0a[k] + 1.0f) * 111.5f;

        float py = (float)y + f1a[k];
        float pz = (float)z + f2a[k];
        py = fminf(fmaxf(py, 0.0f), (float)(HH - 1));
        pz = fminf(fmaxf(pz, 0.0f), (float)(DD - 1));

        const float y0f = floorf(py);
        const float z0f = floorf(pz);
        const float fy = py - y0f;
        const float fz = pz - z0f;
        const int y0 = (int)y0f;
        const int z0 = (int)z0f;

        float res;
        if (pxr >= (float)(WW - 1)) {
            // border fast path: fx == 0; all 4 corners in one packed LDG.128
            const float4 v = __ldg(bs4 + z0 * HH + y0);
            const float c0 = v.x + (v.y - v.x) * fy;
            const float c1 = v.z + (v.w - v.z) * fy;
            res = c0 + (c1 - c0) * fz;
        } else {
            const float px = fmaxf(pxr, 0.0f);      // px < 223 here
            const float x0f = floorf(px);
            const float fx = px - x0f;
            const int x0 = (int)x0f;
            const int x1 = min(x0 + 1, WW - 1);
            const int y1 = min(y0 + 1, HH - 1);
            const int z1 = min(z0 + 1, DD - 1);

            const long long zb0 = (long long)z0 * HW;
            const long long zb1 = (long long)z1 * HW;
            const int yb0 = y0 * WW;
            const int yb1 = y1 * WW;

            const float c000 = __ldg(im + zb0 + yb0 + x0);
            const float c001 = __ldg(im + zb0 + yb0 + x1);
            const float c010 = __ldg(im + zb0 + yb1 + x0);
            const float c011 = __ldg(im + zb0 + yb1 + x1);
            const float c100 = __ldg(im + zb1 + yb0 + x0);
            const float c101 = __ldg(im + zb1 + yb0 + x1);
            const float c110 = __ldg(im + zb1 + yb1 + x0);
            const float c111 = __ldg(im + zb1 + yb1 + x1);

            const float c00 = c000 + (c001 - c000) * fx;
            const float c01 = c010 + (c011 - c010) * fx;
            const float c10 = c100 + (c101 - c100) * fx;
            const float c11 = c110 + (c111 - c110) * fx;
            const float c0 = c00 + (c01 - c00) * fy;
            const float c1 = c10 + (c11 - c10) * fy;
            res = c0 + (c1 - c0) * fz;
        }
        oa[k] = res;
    }

    float* ob = out + (size_t)b * NVOX + i;
    __stcs(reinterpret_cast<float4*>(ob), make_float4(oa[0], oa[1], oa[2], oa[3]));
}

extern "C" void kernel_launch(void* const* d_in, const int* in_sizes, int n_in,
                              void* d_out, int out_size)
{
    const float* img  = (const float*)d_in[0];
    const float* flow = (const float*)d_in[1];
    float* out = (float*)d_out;

    build_bs4_kernel<<<(NSLICE + 255) / 256, 256>>>(img);

    const long long total4 = (long long)NB * NVOX / 4;   // 3,440,640 threads
    const int threads = 256;
    const int blocks = (int)((total4 + threads - 1) / threads);
    st3d_kernel<<<blocks, threads>>>(img, flow, out);
}